// round 8
// baseline (speedup 1.0000x reference)
#include <cuda_runtime.h>
#include <cuda_bf16.h>

// RegionSelector: sampling_map [B=128, 1, 512, 512] fp32.
// GRID=4 -> 16 cells of 128x128. WIN=3 -> n=2 -> four 3x3 windows. TOPK=1.
// Output [B, 1, 2] float32 = (row, col) of argmax window.
//
// 256 CTAs (2 halves x 128 batches) x 512 thr. Each CTA streams a 256-row
// half-image (512KB) with R4's proven shape: 64 float4 loads/thread, 4-way
// batched. Partials -> unique scratch slots (deterministic). Last CTA per
// batch (atomic counter to 2) folds 16 cell sums, does the 2x2 window
// argmax, writes (row,col) as floats, resets counter (graph-replay safe).

#define B_    128
#define HW    512
#define HW4   (HW / 4)       // 128 float4 per image row
#define NT    512

__device__ float        g_partial[B_ * 16];   // [b][rowcell][colcell]
__device__ unsigned int g_count[B_];          // zero-init; reset after use

__global__ __launch_bounds__(NT, 2)
void region_selector_kernel(const float* __restrict__ in, float* __restrict__ out) {
    const int half = blockIdx.x;         // 0..1  (rows half*256 .. half*256+255)
    const int b    = blockIdx.y;         // 0..127
    const int tid  = threadIdx.x;

    const float4* __restrict__ base = reinterpret_cast<const float4*>(
        in + (size_t)b * (HW * HW) + (size_t)half * 256 * HW);

    // c = tid & 127 -> float4 column (0..127); rphase = tid >> 7 (0..3).
    // Rows r = rphase + 4k (k=0..31) in each of the 2 row-cells of this half.
    // Warp load = 32 consecutive float4 = 512B contiguous.
    const int c       = tid & 127;
    const int rphase  = tid >> 7;        // 0..3, uniform per warp
    const int colcell = c >> 5;          // 0..3, uniform per warp
    const int lane    = tid & 31;

    float s0 = 0.f, s1 = 0.f;

    #pragma unroll 4
    for (int k = 0; k < 32; k++) {
        const int r = rphase + 4 * k;    // 0..127 within a row-cell
        float4 v0 = __ldg(base + (size_t)(r +   0) * HW4 + c);   // row-cell half*2+0
        float4 v1 = __ldg(base + (size_t)(r + 128) * HW4 + c);   // row-cell half*2+1
        s0 += (v0.x + v0.y) + (v0.z + v0.w);
        s1 += (v1.x + v1.y) + (v1.z + v1.w);
    }

    // Warp reduce both row-cell partials.
    #pragma unroll
    for (int off = 16; off > 0; off >>= 1) {
        s0 += __shfl_down_sync(0xFFFFFFFFu, s0, off);
        s1 += __shfl_down_sync(0xFFFFFFFFu, s1, off);
    }

    // partial[rc_local][colcell][rphase]; (colcell, rphase) unique per warp.
    __shared__ float partial[2][4][4];
    __shared__ unsigned int s_last;
    if (lane == 0) {
        partial[0][colcell][rphase] = s0;
        partial[1][colcell][rphase] = s1;
    }
    __syncthreads();

    // Fold the 4 rphase copies; write this half's 8 cell sums to scratch.
    if (tid < 8) {
        const int rc_local = tid >> 2;   // 0..1
        const int cc       = tid & 3;    // 0..3
        const float t = partial[rc_local][cc][0] + partial[rc_local][cc][1]
                      + partial[rc_local][cc][2] + partial[rc_local][cc][3];
        g_partial[b * 16 + (half * 2 + rc_local) * 4 + cc] = t;
    }
    __syncthreads();

    if (tid == 0) {
        __threadfence();
        s_last = atomicAdd(&g_count[b], 1u);
    }
    __syncthreads();
    if (s_last != 1u) return;            // not the last of the 2 CTAs

    if (tid == 0) {
        g_count[b] = 0;                  // reset for next graph replay
        __threadfence();                 // acquire partner's partials
        const float* p = g_partial + b * 16;
        float cell[16];
        #pragma unroll
        for (int i = 0; i < 16; i++) cell[i] = p[i];

        // Four 3x3 windows over the 4x4 grid (n = 2). Argmax invariant to
        // the uniform 1/16384 mean scaling. Strict > => lowest idx on ties.
        float best = -3.402823466e+38f;
        int best_idx = 0;
        #pragma unroll
        for (int r = 0; r < 2; r++) {
            #pragma unroll
            for (int cw = 0; cw < 2; cw++) {
                float w = 0.f;
                #pragma unroll
                for (int dr = 0; dr < 3; dr++)
                    #pragma unroll
                    for (int dc = 0; dc < 3; dc++)
                        w += cell[(r + dr) * 4 + (cw + dc)];
                const int idx = r * 2 + cw;
                if (w > best) { best = w; best_idx = idx; }
            }
        }
        out[b * 2 + 0] = (float)(best_idx >> 1);   // row = idx / n
        out[b * 2 + 1] = (float)(best_idx & 1);    // col = idx % n
    }
}

extern "C" void kernel_launch(void* const* d_in, const int* in_sizes, int n_in,
                              void* d_out, int out_size) {
    const float* in = (const float*)d_in[0];
    float* out = (float*)d_out;
    dim3 grid(2, B_);
    region_selector_kernel<<<grid, NT>>>(in, out);
}